// round 1
// baseline (speedup 1.0000x reference)
#include <cuda_runtime.h>
#include <math.h>

#define BB 4
#define SS 2048
#define EMB 1024
#define NH 16
#define DH 64
#define MROWS (BB*SS)   /* 8192 */
#define HD (NH*DH)      /* 1024 */

// Scratch (module-load allocated, not runtime alloc)
__device__ float g_Q[BB*NH*SS*DH];
__device__ float g_K[BB*NH*SS*DH];
__device__ float g_V[BB*NH*SS*DH];
__device__ float g_O[MROWS*HD];

// ---------------------------------------------------------------------------
// GEMM tiling constants: C[M,N] = A[M,K] * W[N,K]^T   (both K-major)
// 128x128 tile, BK=16, 256 threads, 8x8 register tile per thread.
// ---------------------------------------------------------------------------
#define BM 128
#define BN 128
#define BK 16
#define LDT (BM + 4)   /* 132, keeps 16B alignment (132%4==0) */

// ---------------------------------------------------------------------------
// Kernel 1: QKV projection. blockIdx.z selects Q/K/V.
// Writes to g_Q/g_K/g_V in [B,H,S,DH] layout; Q gets *0.125 (1/sqrt(64)).
// ---------------------------------------------------------------------------
__global__ __launch_bounds__(256, 2)
void qkv_proj_kernel(const float* __restrict__ x,
                     const float* __restrict__ Wq, const float* __restrict__ bq,
                     const float* __restrict__ Wk, const float* __restrict__ bk,
                     const float* __restrict__ Wv, const float* __restrict__ bv)
{
    const int which = blockIdx.z;
    const float* __restrict__ W = (which == 0) ? Wq : (which == 1) ? Wk : Wv;
    const float* __restrict__ bias = (which == 0) ? bq : (which == 1) ? bk : bv;
    float* __restrict__ dst = (which == 0) ? g_Q : (which == 1) ? g_K : g_V;

    __shared__ float As[BK][LDT];
    __shared__ float Bs[BK][LDT];

    const int tid = threadIdx.x;
    const int tr = tid / 16;
    const int tc = tid % 16;
    const int row0 = blockIdx.x * BM;
    const int col0 = blockIdx.y * BN;

    float acc[8][8];
#pragma unroll
    for (int i = 0; i < 8; i++)
#pragma unroll
        for (int j = 0; j < 8; j++) acc[i][j] = 0.0f;

    for (int k0 = 0; k0 < EMB; k0 += BK) {
        // Load A tile (128x16) and B tile (128x16), store transposed [k][row].
#pragma unroll
        for (int u = 0; u < 2; u++) {
            int idx = tid + u * 256;       // 0..511
            int r   = idx >> 2;            // 0..127
            int c4  = (idx & 3) * 4;       // 0,4,8,12
            float4 va = *(const float4*)&x[(size_t)(row0 + r) * EMB + k0 + c4];
            As[c4 + 0][r] = va.x; As[c4 + 1][r] = va.y;
            As[c4 + 2][r] = va.z; As[c4 + 3][r] = va.w;
            float4 vb = *(const float4*)&W[(size_t)(col0 + r) * EMB + k0 + c4];
            Bs[c4 + 0][r] = vb.x; Bs[c4 + 1][r] = vb.y;
            Bs[c4 + 2][r] = vb.z; Bs[c4 + 3][r] = vb.w;
        }
        __syncthreads();

#pragma unroll
        for (int kk = 0; kk < BK; kk++) {
            float a[8], b[8];
            *(float4*)&a[0] = *(float4*)&As[kk][tr * 8];
            *(float4*)&a[4] = *(float4*)&As[kk][tr * 8 + 4];
            *(float4*)&b[0] = *(float4*)&Bs[kk][tc * 8];
            *(float4*)&b[4] = *(float4*)&Bs[kk][tc * 8 + 4];
#pragma unroll
            for (int i = 0; i < 8; i++)
#pragma unroll
                for (int j = 0; j < 8; j++)
                    acc[i][j] = fmaf(a[i], b[j], acc[i][j]);
        }
        __syncthreads();
    }

    const float qscale = (which == 0) ? 0.125f : 1.0f;
#pragma unroll
    for (int i = 0; i < 8; i++) {
        int m = row0 + tr * 8 + i;
        int b_idx = m >> 11;         // /2048
        int s_idx = m & 2047;
#pragma unroll
        for (int j = 0; j < 8; j++) {
            int n = col0 + tc * 8 + j;
            int h  = n >> 6;
            int dh = n & 63;
            float v = (acc[i][j] + bias[n]) * qscale;
            dst[(((size_t)b_idx * NH + h) * SS + s_idx) * DH + dh] = v;
        }
    }
}

// ---------------------------------------------------------------------------
// Kernel 2: flash attention, fp32. One CTA = (b,h) x 64-query tile.
// 256 threads; thread tile 4x4; online softmax with 16-lane shuffle reduce.
// Dynamic smem: Qs_t,Ks_t,Vs,Ps_t each [64][68] floats = 69632 B.
// ---------------------------------------------------------------------------
#define AQT 64          /* query tile */
#define AKT 64          /* kv tile */
#define ALD 68          /* padded stride */
#define ATT_SMEM (4 * 64 * ALD * sizeof(float))

__global__ __launch_bounds__(256, 2)
void attention_kernel()
{
    extern __shared__ float sm[];
    float* Qs = sm;                 // [DH][ALD]  (d-major, col = q)
    float* Ks = sm + 64 * ALD;      // [DH][ALD]  (d-major, col = kv)
    float* Vs = sm + 2 * 64 * ALD;  // [AKT][ALD] (kv-major, col = dh)
    float* Ps = sm + 3 * 64 * ALD;  // [AKT][ALD] (kv-major, col = q)

    const int tid = threadIdx.x;
    const int tr = tid / 16;        // q-row group (4 rows)
    const int tc = tid % 16;        // col group (4 cols)
    const int qt = blockIdx.x;      // query tile (0..31)
    const int bh = blockIdx.y;      // b*H + h   (0..63)
    const int q0 = qt * AQT;

    const float* __restrict__ Qg = g_Q + (size_t)bh * SS * DH;
    const float* __restrict__ Kg = g_K + (size_t)bh * SS * DH;
    const float* __restrict__ Vg = g_V + (size_t)bh * SS * DH;

    // Load Q tile transposed: Qs[d][q]
#pragma unroll
    for (int u = 0; u < 4; u++) {
        int idx = tid + u * 256;        // 0..1023
        int r   = idx >> 4;             // 0..63 (q row)
        int c4  = (idx & 15) * 4;       // d
        float4 v = *(const float4*)&Qg[(size_t)(q0 + r) * DH + c4];
        Qs[(c4 + 0) * ALD + r] = v.x; Qs[(c4 + 1) * ALD + r] = v.y;
        Qs[(c4 + 2) * ALD + r] = v.z; Qs[(c4 + 3) * ALD + r] = v.w;
    }

    float mrow[4], lrow[4], o[4][4];
#pragma unroll
    for (int i = 0; i < 4; i++) {
        mrow[i] = -INFINITY; lrow[i] = 0.0f;
#pragma unroll
        for (int j = 0; j < 4; j++) o[i][j] = 0.0f;
    }

    for (int kt = 0; kt < SS / AKT; kt++) {
        __syncthreads();   // previous iteration's reads of Ks/Vs/Ps done
        const int k0 = kt * AKT;
#pragma unroll
        for (int u = 0; u < 4; u++) {
            int idx = tid + u * 256;
            int r   = idx >> 4;
            int c4  = (idx & 15) * 4;
            float4 v = *(const float4*)&Kg[(size_t)(k0 + r) * DH + c4];
            Ks[(c4 + 0) * ALD + r] = v.x; Ks[(c4 + 1) * ALD + r] = v.y;
            Ks[(c4 + 2) * ALD + r] = v.z; Ks[(c4 + 3) * ALD + r] = v.w;
            float4 w = *(const float4*)&Vg[(size_t)(k0 + r) * DH + c4];
            *(float4*)&Vs[r * ALD + c4] = w;
        }
        __syncthreads();

        // S = Q * K^T  (4x4 per thread)
        float s4[4][4];
#pragma unroll
        for (int i = 0; i < 4; i++)
#pragma unroll
            for (int j = 0; j < 4; j++) s4[i][j] = 0.0f;
#pragma unroll 4
        for (int d = 0; d < DH; d++) {
            float4 a = *(float4*)&Qs[d * ALD + tr * 4];
            float4 b = *(float4*)&Ks[d * ALD + tc * 4];
            float av[4] = {a.x, a.y, a.z, a.w};
            float bv[4] = {b.x, b.y, b.z, b.w};
#pragma unroll
            for (int i = 0; i < 4; i++)
#pragma unroll
                for (int j = 0; j < 4; j++)
                    s4[i][j] = fmaf(av[i], bv[j], s4[i][j]);
        }

        // Online softmax per row (16 lanes share a row group)
        float p4[4][4];
#pragma unroll
        for (int i = 0; i < 4; i++) {
            float tmax = s4[i][0];
#pragma unroll
            for (int j = 1; j < 4; j++) tmax = fmaxf(tmax, s4[i][j]);
#pragma unroll
            for (int off = 8; off > 0; off >>= 1)
                tmax = fmaxf(tmax, __shfl_xor_sync(0xffffffffu, tmax, off));
            float mnew = fmaxf(mrow[i], tmax);
            float alpha = __expf(mrow[i] - mnew);
            mrow[i] = mnew;
            float rsum = 0.0f;
#pragma unroll
            for (int j = 0; j < 4; j++) {
                p4[i][j] = __expf(s4[i][j] - mnew);
                rsum += p4[i][j];
            }
#pragma unroll
            for (int off = 8; off > 0; off >>= 1)
                rsum += __shfl_xor_sync(0xffffffffu, rsum, off);
            lrow[i] = lrow[i] * alpha + rsum;
#pragma unroll
            for (int j = 0; j < 4; j++) o[i][j] *= alpha;
        }

        // Stage P transposed: Ps[kv][q]
#pragma unroll
        for (int i = 0; i < 4; i++)
#pragma unroll
            for (int j = 0; j < 4; j++)
                Ps[(tc * 4 + j) * ALD + (tr * 4 + i)] = p4[i][j];
        __syncthreads();

        // O += P * V   (thread: rows=q group tr, cols=dh group tc)
#pragma unroll 4
        for (int t = 0; t < AKT; t++) {
            float4 pa = *(float4*)&Ps[t * ALD + tr * 4];
            float4 vb = *(float4*)&Vs[t * ALD + tc * 4];
            float pv[4] = {pa.x, pa.y, pa.z, pa.w};
            float vv[4] = {vb.x, vb.y, vb.z, vb.w};
#pragma unroll
            for (int i = 0; i < 4; i++)
#pragma unroll
                for (int j = 0; j < 4; j++)
                    o[i][j] = fmaf(pv[i], vv[j], o[i][j]);
        }
    }

    // Write O: [B,S,H*DH] layout for the output projection
    const int b_idx = bh >> 4;
    const int h     = bh & 15;
#pragma unroll
    for (int i = 0; i < 4; i++) {
        int s_idx = q0 + tr * 4 + i;
        float inv_l = 1.0f / lrow[i];
#pragma unroll
        for (int j = 0; j < 4; j++) {
            int dh = tc * 4 + j;
            g_O[((size_t)b_idx * SS + s_idx) * HD + h * DH + dh] = o[i][j] * inv_l;
        }
    }
}

// ---------------------------------------------------------------------------
// Kernel 3: output projection: out[m,e] = sum_d O[m,d]*Wo[e,d] + bo[e]
// ---------------------------------------------------------------------------
__global__ __launch_bounds__(256, 2)
void out_proj_kernel(const float* __restrict__ Wo, const float* __restrict__ bo,
                     float* __restrict__ out)
{
    __shared__ float As[BK][LDT];
    __shared__ float Bs[BK][LDT];

    const int tid = threadIdx.x;
    const int tr = tid / 16;
    const int tc = tid % 16;
    const int row0 = blockIdx.x * BM;
    const int col0 = blockIdx.y * BN;

    float acc[8][8];
#pragma unroll
    for (int i = 0; i < 8; i++)
#pragma unroll
        for (int j = 0; j < 8; j++) acc[i][j] = 0.0f;

    for (int k0 = 0; k0 < HD; k0 += BK) {
#pragma unroll
        for (int u = 0; u < 2; u++) {
            int idx = tid + u * 256;
            int r   = idx >> 2;
            int c4  = (idx & 3) * 4;
            float4 va = *(const float4*)&g_O[(size_t)(row0 + r) * HD + k0 + c4];
            As[c4 + 0][r] = va.x; As[c4 + 1][r] = va.y;
            As[c4 + 2][r] = va.z; As[c4 + 3][r] = va.w;
            float4 vb = *(const float4*)&Wo[(size_t)(col0 + r) * HD + k0 + c4];
            Bs[c4 + 0][r] = vb.x; Bs[c4 + 1][r] = vb.y;
            Bs[c4 + 2][r] = vb.z; Bs[c4 + 3][r] = vb.w;
        }
        __syncthreads();

#pragma unroll
        for (int kk = 0; kk < BK; kk++) {
            float a[8], b[8];
            *(float4*)&a[0] = *(float4*)&As[kk][tr * 8];
            *(float4*)&a[4] = *(float4*)&As[kk][tr * 8 + 4];
            *(float4*)&b[0] = *(float4*)&Bs[kk][tc * 8];
            *(float4*)&b[4] = *(float4*)&Bs[kk][tc * 8 + 4];
#pragma unroll
            for (int i = 0; i < 8; i++)
#pragma unroll
                for (int j = 0; j < 8; j++)
                    acc[i][j] = fmaf(a[i], b[j], acc[i][j]);
        }
        __syncthreads();
    }

#pragma unroll
    for (int i = 0; i < 8; i++) {
        int m = row0 + tr * 8 + i;
#pragma unroll
        for (int j = 0; j < 8; j++) {
            int n = col0 + tc * 8 + j;
            out[(size_t)m * EMB + n] = acc[i][j] + bo[n];
        }
    }
}

// ---------------------------------------------------------------------------
extern "C" void kernel_launch(void* const* d_in, const int* in_sizes, int n_in,
                              void* d_out, int out_size)
{
    const float* x  = (const float*)d_in[0];
    const float* Wq = (const float*)d_in[1];
    const float* bq = (const float*)d_in[2];
    const float* Wk = (const float*)d_in[3];
    const float* bk = (const float*)d_in[4];
    const float* Wv = (const float*)d_in[5];
    const float* bv = (const float*)d_in[6];
    const float* Wo = (const float*)d_in[7];
    const float* bo = (const float*)d_in[8];
    float* out = (float*)d_out;

    cudaFuncSetAttribute(attention_kernel,
                         cudaFuncAttributeMaxDynamicSharedMemorySize,
                         (int)ATT_SMEM);

    dim3 gProj(MROWS / BM, HD / BN, 3);       // 64 x 8 x 3
    qkv_proj_kernel<<<gProj, 256>>>(x, Wq, bq, Wk, bk, Wv, bv);

    dim3 gAtt(SS / AQT, BB * NH);             // 32 x 64
    attention_kernel<<<gAtt, 256, ATT_SMEM>>>();

    dim3 gOut(MROWS / BM, EMB / BN);          // 64 x 8
    out_proj_kernel<<<gOut, 256>>>(Wo, bo, out);
}

// round 3
// speedup vs baseline: 1.7484x; 1.7484x over previous
#include <cuda_runtime.h>
#include <cuda_bf16.h>
#include <math.h>
#include <stdint.h>

#define BB 4
#define SS 2048
#define EMB 1024
#define NH 16
#define DH 64
#define MROWS (BB*SS)   /* 8192 */
#define HD (NH*DH)      /* 1024 */

__device__ float g_Q[BB*NH*SS*DH];
__device__ float g_K[BB*NH*SS*DH];
__device__ float g_V[BB*NH*SS*DH];
__device__ float g_O[MROWS*HD];

__device__ __forceinline__ void mma_bf16(float d[4], uint32_t a0, uint32_t a1,
                                         uint32_t a2, uint32_t a3,
                                         uint32_t b0, uint32_t b1) {
    asm volatile(
        "mma.sync.aligned.m16n8k16.row.col.f32.bf16.bf16.f32 "
        "{%0,%1,%2,%3}, {%4,%5,%6,%7}, {%8,%9}, {%0,%1,%2,%3};\n"
        : "+f"(d[0]), "+f"(d[1]), "+f"(d[2]), "+f"(d[3])
        : "r"(a0), "r"(a1), "r"(a2), "r"(a3), "r"(b0), "r"(b1));
}

__device__ __forceinline__ uint32_t b2u(__nv_bfloat162 v) {
    return *reinterpret_cast<uint32_t*>(&v);
}

// split two floats into (hi bf16x2, lo bf16x2) packed in uint2
__device__ __forceinline__ uint2 bsplit(float x0, float x1) {
    __nv_bfloat162 h = __floats2bfloat162_rn(x0, x1);
    float r0 = x0 - __low2float(h);
    float r1 = x1 - __high2float(h);
    __nv_bfloat162 l = __floats2bfloat162_rn(r0, r1);
    uint2 w; w.x = b2u(h); w.y = b2u(l);
    return w;
}

// ---------------------------------------------------------------------------
// Projection GEMM: C[M,N] = A[M,K] * W[N,K]^T (+bias), split-bf16 3-MMA.
// 128x128 tile, BK=16 (one k16 step), 256 threads, warp tile 64x32.
// smem word = uint2(hi2,lo2), row stride 12 (8 data pairs + 4 pad).
// ---------------------------------------------------------------------------
#define PST 12

#define PROJ_MAINLOOP(APTR, BPTR, KDIM)                                          \
    float acc[4][4][4];                                                          \
    _Pragma("unroll") for (int i = 0; i < 4; i++)                                \
    _Pragma("unroll") for (int j = 0; j < 4; j++)                                \
    _Pragma("unroll") for (int e = 0; e < 4; e++) acc[i][j][e] = 0.0f;           \
    const int r0 = tid >> 2;                                                     \
    const int c4 = (tid & 3) << 2;                                               \
    const int p0 = (tid & 3) << 1;                                               \
    float4 fa0, fa1, fb0, fb1;                                                   \
    fa0 = *(const float4*)&(APTR)[(size_t)(row0 + r0) * (KDIM) + c4];            \
    fa1 = *(const float4*)&(APTR)[(size_t)(row0 + r0 + 64) * (KDIM) + c4];       \
    fb0 = *(const float4*)&(BPTR)[(size_t)(col0 + r0) * (KDIM) + c4];            \
    fb1 = *(const float4*)&(BPTR)[(size_t)(col0 + r0 + 64) * (KDIM) + c4];       \
    for (int k0 = 0; k0 < (KDIM); k0 += 16) {                                    \
        As[r0][p0]          = bsplit(fa0.x, fa0.y);                              \
        As[r0][p0 + 1]      = bsplit(fa0.z, fa0.w);                              \
        As[r0 + 64][p0]     = bsplit(fa1.x, fa1.y);                              \
        As[r0 + 64][p0 + 1] = bsplit(fa1.z, fa1.w);                              \
        Bs[r0][p0]          = bsplit(fb0.x, fb0.y);                              \
        Bs[r0][p0 + 1]      = bsplit(fb0.z, fb0.w);                              \
        Bs[r0 + 64][p0]     = bsplit(fb1.x, fb1.y);                              \
        Bs[r0 + 64][p0 + 1] = bsplit(fb1.z, fb1.w);                              \
        __syncthreads();                                                         \
        if (k0 + 16 < (KDIM)) {                                                  \
            fa0 = *(const float4*)&(APTR)[(size_t)(row0 + r0) * (KDIM) + k0 + 16 + c4];      \
            fa1 = *(const float4*)&(APTR)[(size_t)(row0 + r0 + 64) * (KDIM) + k0 + 16 + c4]; \
            fb0 = *(const float4*)&(BPTR)[(size_t)(col0 + r0) * (KDIM) + k0 + 16 + c4];      \
            fb1 = *(const float4*)&(BPTR)[(size_t)(col0 + r0 + 64) * (KDIM) + k0 + 16 + c4]; \
        }                                                                        \
        uint32_t bh[4][2], bl[4][2];                                             \
        _Pragma("unroll")                                                        \
        for (int nt = 0; nt < 4; nt++) {                                         \
            int cb = wn * 32 + nt * 8 + g;                                       \
            uint2 w0 = Bs[cb][t];                                                \
            uint2 w1 = Bs[cb][t + 4];                                            \
            bh[nt][0] = w0.x; bl[nt][0] = w0.y;                                  \
            bh[nt][1] = w1.x; bl[nt][1] = w1.y;                                  \
        }                                                                        \
        _Pragma("unroll")                                                        \
        for (int mt = 0; mt < 4; mt++) {                                         \
            int rb = wm * 64 + mt * 16 + g;                                      \
            uint2 a0 = As[rb][t], a1 = As[rb + 8][t];                            \
            uint2 a2 = As[rb][t + 4], a3 = As[rb + 8][t + 4];                    \
            _Pragma("unroll")                                                    \
            for (int nt = 0; nt < 4; nt++) {                                     \
                mma_bf16(acc[mt][nt], a0.x, a1.x, a2.x, a3.x, bh[nt][0], bh[nt][1]); \
                mma_bf16(acc[mt][nt], a0.x, a1.x, a2.x, a3.x, bl[nt][0], bl[nt][1]); \
                mma_bf16(acc[mt][nt], a0.y, a1.y, a2.y, a3.y, bh[nt][0], bh[nt][1]); \
            }                                                                    \
        }                                                                        \
        __syncthreads();                                                         \
    }

__global__ __launch_bounds__(256, 2)
void qkv_proj_kernel(const float* __restrict__ x,
                     const float* __restrict__ Wq, const float* __restrict__ bq,
                     const float* __restrict__ Wk, const float* __restrict__ bk,
                     const float* __restrict__ Wv, const float* __restrict__ bv)
{
    const int which = blockIdx.z;
    const float* __restrict__ W = (which == 0) ? Wq : (which == 1) ? Wk : Wv;
    const float* __restrict__ bias = (which == 0) ? bq : (which == 1) ? bk : bv;
    float* __restrict__ dst = (which == 0) ? g_Q : (which == 1) ? g_K : g_V;
    const float qscale = (which == 0) ? 0.125f : 1.0f;

    __shared__ uint2 As[128][PST];
    __shared__ uint2 Bs[128][PST];

    const int tid = threadIdx.x;
    const int lane = tid & 31;
    const int warp = tid >> 5;
    const int wm = warp >> 2, wn = warp & 3;
    const int g = lane >> 2, t = lane & 3;
    const int row0 = blockIdx.x * 128;
    const int col0 = blockIdx.y * 128;

    PROJ_MAINLOOP(x, W, EMB)

#pragma unroll
    for (int mt = 0; mt < 4; mt++) {
#pragma unroll
        for (int nt = 0; nt < 4; nt++) {
            int n = col0 + wn * 32 + nt * 8 + 2 * t;
            int h = n >> 6, dh = n & 63;
            float2 bv2 = *(const float2*)&bias[n];
#pragma unroll
            for (int rr = 0; rr < 2; rr++) {
                int m = row0 + wm * 64 + mt * 16 + g + rr * 8;
                int b_idx = m >> 11;
                int s_idx = m & 2047;
                float2 o2;
                o2.x = (acc[mt][nt][rr * 2 + 0] + bv2.x) * qscale;
                o2.y = (acc[mt][nt][rr * 2 + 1] + bv2.y) * qscale;
                *(float2*)&dst[(((size_t)b_idx * NH + h) * SS + s_idx) * DH + dh] = o2;
            }
        }
    }
}

__global__ __launch_bounds__(256, 2)
void out_proj_kernel(const float* __restrict__ Wo, const float* __restrict__ bo,
                     float* __restrict__ out)
{
    __shared__ uint2 As[128][PST];
    __shared__ uint2 Bs[128][PST];

    const int tid = threadIdx.x;
    const int lane = tid & 31;
    const int warp = tid >> 5;
    const int wm = warp >> 2, wn = warp & 3;
    const int g = lane >> 2, t = lane & 3;
    const int row0 = blockIdx.x * 128;
    const int col0 = blockIdx.y * 128;

    PROJ_MAINLOOP(g_O, Wo, HD)

#pragma unroll
    for (int mt = 0; mt < 4; mt++) {
#pragma unroll
        for (int nt = 0; nt < 4; nt++) {
            int n = col0 + wn * 32 + nt * 8 + 2 * t;
            float2 bv2 = *(const float2*)&bo[n];
#pragma unroll
            for (int rr = 0; rr < 2; rr++) {
                int m = row0 + wm * 64 + mt * 16 + g + rr * 8;
                float2 o2;
                o2.x = acc[mt][nt][rr * 2 + 0] + bv2.x;
                o2.y = acc[mt][nt][rr * 2 + 1] + bv2.y;
                *(float2*)&out[(size_t)m * EMB + n] = o2;
            }
        }
    }
}

// ---------------------------------------------------------------------------
// Flash attention, split-bf16. CTA = 128 q x (b,h). 8 warps, warp = 16 q rows.
// S[q][kv] = Q K^T (Q regs, K natural pair-major-d smem).
// O[q][dh] += P V  (P natural pair-major-kv from C-frags, V staged pair-major-kv).
// Softmax state lives entirely in C-fragment rows (no smem handoff).
// ---------------------------------------------------------------------------
#define AQ 128
#define AK 64
#define KST 36  /* 32 data pairs + 4 pad, uint2 units */
#define ATT_SMEM ((64*KST + 64*KST + 128*KST) * sizeof(uint2))

__global__ __launch_bounds__(256)
void attention_kernel()
{
    extern __shared__ uint2 smu[];
    uint2 (*Ks)[KST] = (uint2(*)[KST])smu;              // [64 kv][32 d-pairs]
    uint2 (*Vp)[KST] = (uint2(*)[KST])(smu + 64 * KST); // [64 dh][32 kv-pairs]
    uint2 (*Ps)[KST] = (uint2(*)[KST])(smu + 128 * KST);// [128 q][32 kv-pairs]

    const int tid = threadIdx.x;
    const int lane = tid & 31;
    const int w = tid >> 5;
    const int g = lane >> 2, t = lane & 3;
    const int q0 = blockIdx.x * AQ;
    const int bh = blockIdx.y;

    const float* __restrict__ Qg = g_Q + ((size_t)bh * SS + q0 + w * 16) * DH;
    const float* __restrict__ Kg = g_K + (size_t)bh * SS * DH;
    const float* __restrict__ Vg = g_V + (size_t)bh * SS * DH;

    // Q fragments (pairs along d): 4 k16-tiles, hi/lo
    uint32_t qh[4][4], ql[4][4];
#pragma unroll
    for (int kt = 0; kt < 4; kt++) {
        float2 f0 = *(const float2*)&Qg[(size_t)g * DH + kt * 16 + 2 * t];
        float2 f1 = *(const float2*)&Qg[(size_t)(g + 8) * DH + kt * 16 + 2 * t];
        float2 f2 = *(const float2*)&Qg[(size_t)g * DH + kt * 16 + 2 * t + 8];
        float2 f3 = *(const float2*)&Qg[(size_t)(g + 8) * DH + kt * 16 + 2 * t + 8];
        uint2 s0 = bsplit(f0.x, f0.y), s1 = bsplit(f1.x, f1.y);
        uint2 s2 = bsplit(f2.x, f2.y), s3 = bsplit(f3.x, f3.y);
        qh[kt][0] = s0.x; ql[kt][0] = s0.y;
        qh[kt][1] = s1.x; ql[kt][1] = s1.y;
        qh[kt][2] = s2.x; ql[kt][2] = s2.y;
        qh[kt][3] = s3.x; ql[kt][3] = s3.y;
    }

    float oacc[8][4];
#pragma unroll
    for (int nt = 0; nt < 8; nt++)
#pragma unroll
        for (int e = 0; e < 4; e++) oacc[nt][e] = 0.0f;
    float m0 = -INFINITY, m1 = -INFINITY, l0 = 0.0f, l1 = 0.0f;

    __nv_bfloat16* vp16 = reinterpret_cast<__nv_bfloat16*>(&Vp[0][0]);

    for (int kv0 = 0; kv0 < SS; kv0 += AK) {
        __syncthreads();   // previous iteration's Ks/Vp reads done
        // Load K (pairs along d) and V (pairs along kv) tiles
#pragma unroll
        for (int u = 0; u < 4; u++) {
            int idx = tid + u * 256;
            int r = idx >> 4;              // kv row 0..63
            int c4 = (idx & 15) << 2;      // dh 0..60
            float4 fk = *(const float4*)&Kg[(size_t)(kv0 + r) * DH + c4];
            Ks[r][c4 / 2]     = bsplit(fk.x, fk.y);
            Ks[r][c4 / 2 + 1] = bsplit(fk.z, fk.w);
            float4 fv = *(const float4*)&Vg[(size_t)(kv0 + r) * DH + c4];
            float fvv[4] = {fv.x, fv.y, fv.z, fv.w};
#pragma unroll
            for (int i = 0; i < 4; i++) {
                __nv_bfloat16 hv = __float2bfloat16_rn(fvv[i]);
                __nv_bfloat16 lv = __float2bfloat16_rn(fvv[i] - __bfloat162float(hv));
                int base = ((c4 + i) * KST + (r >> 1)) * 4 + (r & 1);
                vp16[base]     = hv;
                vp16[base + 2] = lv;
            }
        }
        __syncthreads();

        // ---- S = Q K^T : per-warp 16 x 64 ----
        float sacc[8][4];
#pragma unroll
        for (int nt = 0; nt < 8; nt++)
#pragma unroll
            for (int e = 0; e < 4; e++) sacc[nt][e] = 0.0f;
#pragma unroll
        for (int kt = 0; kt < 4; kt++) {
#pragma unroll
            for (int nt = 0; nt < 8; nt++) {
                uint2 w0 = Ks[nt * 8 + g][kt * 8 + t];
                uint2 w1 = Ks[nt * 8 + g][kt * 8 + t + 4];
                mma_bf16(sacc[nt], qh[kt][0], qh[kt][1], qh[kt][2], qh[kt][3], w0.x, w1.x);
                mma_bf16(sacc[nt], qh[kt][0], qh[kt][1], qh[kt][2], qh[kt][3], w0.y, w1.y);
                mma_bf16(sacc[nt], ql[kt][0], ql[kt][1], ql[kt][2], ql[kt][3], w0.x, w1.x);
            }
        }

        // ---- online softmax (rows r0 = w*16+g, r1 = +8) ----
        float mx0 = -INFINITY, mx1 = -INFINITY;
#pragma unroll
        for (int nt = 0; nt < 8; nt++) {
            mx0 = fmaxf(mx0, fmaxf(sacc[nt][0], sacc[nt][1]));
            mx1 = fmaxf(mx1, fmaxf(sacc[nt][2], sacc[nt][3]));
        }
#pragma unroll
        for (int off = 1; off < 4; off <<= 1) {
            mx0 = fmaxf(mx0, __shfl_xor_sync(0xffffffffu, mx0, off));
            mx1 = fmaxf(mx1, __shfl_xor_sync(0xffffffffu, mx1, off));
        }
        float mn0 = fmaxf(m0, mx0), mn1 = fmaxf(m1, mx1);
        float al0 = __expf(m0 - mn0), al1 = __expf(m1 - mn1);
        m0 = mn0; m1 = mn1;
        float rs0 = 0.0f, rs1 = 0.0f;
#pragma unroll
        for (int nt = 0; nt < 8; nt++) {
            sacc[nt][0] = __expf(sacc[nt][0] - mn0);
            sacc[nt][1] = __expf(sacc[nt][1] - mn0);
            sacc[nt][2] = __expf(sacc[nt][2] - mn1);
            sacc[nt][3] = __expf(sacc[nt][3] - mn1);
            rs0 += sacc[nt][0] + sacc[nt][1];
            rs1 += sacc[nt][2] + sacc[nt][3];
        }
#pragma unroll
        for (int off = 1; off < 4; off <<= 1) {
            rs0 += __shfl_xor_sync(0xffffffffu, rs0, off);
            rs1 += __shfl_xor_sync(0xffffffffu, rs1, off);
        }
        l0 = l0 * al0 + rs0;
        l1 = l1 * al1 + rs1;

        // stage P (pairs along kv, warp-local rows)
#pragma unroll
        for (int nt = 0; nt < 8; nt++) {
            Ps[w * 16 + g][nt * 4 + t]     = bsplit(sacc[nt][0], sacc[nt][1]);
            Ps[w * 16 + g + 8][nt * 4 + t] = bsplit(sacc[nt][2], sacc[nt][3]);
        }
        __syncwarp();

        // rescale O (rows owned by this thread directly)
#pragma unroll
        for (int nt = 0; nt < 8; nt++) {
            oacc[nt][0] *= al0; oacc[nt][1] *= al0;
            oacc[nt][2] *= al1; oacc[nt][3] *= al1;
        }

        // ---- O[q][dh] += P V ----
#pragma unroll
        for (int kt = 0; kt < 4; kt++) {
            uint2 a0 = Ps[w * 16 + g][kt * 8 + t];
            uint2 a1 = Ps[w * 16 + g + 8][kt * 8 + t];
            uint2 a2 = Ps[w * 16 + g][kt * 8 + t + 4];
            uint2 a3 = Ps[w * 16 + g + 8][kt * 8 + t + 4];
#pragma unroll
            for (int nt = 0; nt < 8; nt++) {
                uint2 w0 = Vp[nt * 8 + g][kt * 8 + t];
                uint2 w1 = Vp[nt * 8 + g][kt * 8 + t + 4];
                mma_bf16(oacc[nt], a0.x, a1.x, a2.x, a3.x, w0.x, w1.x);
                mma_bf16(oacc[nt], a0.x, a1.x, a2.x, a3.x, w0.y, w1.y);
                mma_bf16(oacc[nt], a0.y, a1.y, a2.y, a3.y, w0.x, w1.x);
            }
        }
    }

    // ---- finalize ----
    const float il0 = 1.0f / l0, il1 = 1.0f / l1;
    const int b_idx = bh >> 4, h = bh & 15;
    float* Og = g_O + ((size_t)b_idx * SS + q0 + w * 16) * HD + h * DH;
#pragma unroll
    for (int nt = 0; nt < 8; nt++) {
        int dh = nt * 8 + 2 * t;
        float2 o0 = make_float2(oacc[nt][0] * il0, oacc[nt][1] * il0);
        float2 o1 = make_float2(oacc[nt][2] * il1, oacc[nt][3] * il1);
        *(float2*)&Og[(size_t)g * HD + dh] = o0;
        *(float2*)&Og[(size_t)(g + 8) * HD + dh] = o1;
    }
}

// ---------------------------------------------------------------------------
extern "C" void kernel_launch(void* const* d_in, const int* in_sizes, int n_in,
                              void* d_out, int out_size)
{
    const float* x  = (const float*)d_in[0];
    const float* Wq = (const float*)d_in[1];
    const float* bq = (const float*)d_in[2];
    const float* Wk = (const float*)d_in[3];
    const float* bk = (const float*)d_in[4];
    const float* Wv = (const float*)d_in[5];
    const float* bv = (const float*)d_in[6];
    const float* Wo = (const float*)d_in[7];
    const float* bo = (const float*)d_in[8];
    float* out = (float*)d_out;

    cudaFuncSetAttribute(attention_kernel,
                         cudaFuncAttributeMaxDynamicSharedMemorySize,
                         (int)ATT_SMEM);

    dim3 gProj(MROWS / 128, HD / 128, 3);
    qkv_proj_kernel<<<gProj, 256>>>(x, Wq, bq, Wk, bk, Wv, bv);

    dim3 gAtt(SS / AQ, BB * NH);
    attention_kernel<<<gAtt, 256, ATT_SMEM>>>();

    dim3 gOut(MROWS / 128, EMB / 128);
    out_proj_kernel<<<gOut, 256>>>(Wo, bo, out);
}

// round 4
// speedup vs baseline: 2.2181x; 1.2687x over previous
#include <cuda_runtime.h>
#include <cuda_bf16.h>
#include <math.h>
#include <stdint.h>

#define BB 4
#define SS 2048
#define EMB 1024
#define NH 16
#define DH 64
#define MROWS (BB*SS)   /* 8192 */
#define HD (NH*DH)      /* 1024 */
#define BH (BB*NH)      /* 64 */

// Pre-split operand planes: uint2 = (bf16x2 hi, bf16x2 lo) for 2 consecutive
// elements along the contraction dimension.
__device__ uint2 g_xs[MROWS*EMB/2];      // x pairs along EMB
__device__ uint2 g_Wqs[HD*EMB/2];
__device__ uint2 g_Wks[HD*EMB/2];
__device__ uint2 g_Wvs[HD*EMB/2];
__device__ uint2 g_Wos[EMB*HD/2];
__device__ uint2 g_Qs[BH*SS*DH/2];       // [bh][s][d-pairs], Q pre-scaled by 0.125
__device__ uint2 g_Ks[BH*SS*DH/2];       // [bh][s][d-pairs]
__device__ float g_V [BH*SS*DH];         // fp32 staging
__device__ uint2 g_Vt[BH*DH*SS/2];       // [bh][dh][kv-pairs]
__device__ float g_O [MROWS*HD];         // attention out fp32
__device__ uint2 g_Os[MROWS*HD/2];       // split of g_O, pairs along HD

__device__ __forceinline__ void mma_bf16(float d[4], uint32_t a0, uint32_t a1,
                                         uint32_t a2, uint32_t a3,
                                         uint32_t b0, uint32_t b1) {
    asm volatile(
        "mma.sync.aligned.m16n8k16.row.col.f32.bf16.bf16.f32 "
        "{%0,%1,%2,%3}, {%4,%5,%6,%7}, {%8,%9}, {%0,%1,%2,%3};\n"
        : "+f"(d[0]), "+f"(d[1]), "+f"(d[2]), "+f"(d[3])
        : "r"(a0), "r"(a1), "r"(a2), "r"(a3), "r"(b0), "r"(b1));
}

__device__ __forceinline__ uint32_t b2u(__nv_bfloat162 v) {
    return *reinterpret_cast<uint32_t*>(&v);
}

__device__ __forceinline__ uint2 bsplit(float x0, float x1) {
    __nv_bfloat162 h = __floats2bfloat162_rn(x0, x1);
    float r0 = x0 - __low2float(h);
    float r1 = x1 - __high2float(h);
    __nv_bfloat162 l = __floats2bfloat162_rn(r0, r1);
    uint2 w; w.x = b2u(h); w.y = b2u(l);
    return w;
}

// ---------------------------------------------------------------------------
// fp32 -> split pair planes (pairs along last dim)
// ---------------------------------------------------------------------------
__global__ void split_kernel(const float* __restrict__ src,
                             uint2* __restrict__ dst, int npairs)
{
    int i = blockIdx.x * blockDim.x + threadIdx.x;
    if (i < npairs) {
        float2 f = ((const float2*)src)[i];
        dst[i] = bsplit(f.x, f.y);
    }
}

// ---------------------------------------------------------------------------
// V transpose+split: g_V [bh][s][dh] fp32 -> g_Vt [bh][dh][s/2] uint2
// ---------------------------------------------------------------------------
__global__ __launch_bounds__(256)
void vtrans_kernel()
{
    __shared__ float sm[64][68];
    const int tid = threadIdx.x;
    const int s0 = blockIdx.x * 64;
    const int bh = blockIdx.y;
    const float* __restrict__ src = g_V + ((size_t)bh * SS + s0) * DH;

#pragma unroll
    for (int u = 0; u < 4; u++) {
        int idx = tid + u * 256;
        int r = idx >> 4;
        int c4 = (idx & 15) << 2;
        *(float4*)&sm[r][c4] = *(const float4*)&src[(size_t)r * DH + c4];
    }
    __syncthreads();

    uint2* __restrict__ dst = g_Vt + (size_t)bh * DH * (SS / 2) + (s0 >> 1);
#pragma unroll
    for (int u = 0; u < 8; u++) {
        int item = tid + u * 256;        // 0..2047
        int dh = item >> 5;
        int sp = item & 31;
        dst[(size_t)dh * (SS / 2) + sp] = bsplit(sm[2 * sp][dh], sm[2 * sp + 1][dh]);
    }
}

// ---------------------------------------------------------------------------
// Projection GEMM on pre-split operands. C = A * B^T (+epilogue).
// 128x128 tile, 16 k-elems (8 pairs) per step, 256 thr, warp tile 64x32.
// ---------------------------------------------------------------------------
#define PST 12

#define PROJ_MAINLOOP(APTR, BPTR, KPAIRS)                                        \
    float acc[4][4][4];                                                          \
    _Pragma("unroll") for (int i = 0; i < 4; i++)                                \
    _Pragma("unroll") for (int j = 0; j < 4; j++)                                \
    _Pragma("unroll") for (int e = 0; e < 4; e++) acc[i][j][e] = 0.0f;           \
    const int r0 = tid >> 2;                                                     \
    const int cp = (tid & 3) << 1;  /* pair idx 0,2,4,6 */                       \
    float4 fa0, fa1, fb0, fb1;                                                   \
    fa0 = *(const float4*)&(APTR)[(size_t)(row0 + r0) * (KPAIRS) + cp];          \
    fa1 = *(const float4*)&(APTR)[(size_t)(row0 + r0 + 64) * (KPAIRS) + cp];     \
    fb0 = *(const float4*)&(BPTR)[(size_t)(col0 + r0) * (KPAIRS) + cp];          \
    fb1 = *(const float4*)&(BPTR)[(size_t)(col0 + r0 + 64) * (KPAIRS) + cp];     \
    for (int kp = 0; kp < (KPAIRS); kp += 8) {                                   \
        *(float4*)&As[r0][cp]      = fa0;                                        \
        *(float4*)&As[r0 + 64][cp] = fa1;                                        \
        *(float4*)&Bs[r0][cp]      = fb0;                                        \
        *(float4*)&Bs[r0 + 64][cp] = fb1;                                        \
        __syncthreads();                                                         \
        if (kp + 8 < (KPAIRS)) {                                                 \
            fa0 = *(const float4*)&(APTR)[(size_t)(row0 + r0) * (KPAIRS) + kp + 8 + cp];      \
            fa1 = *(const float4*)&(APTR)[(size_t)(row0 + r0 + 64) * (KPAIRS) + kp + 8 + cp]; \
            fb0 = *(const float4*)&(BPTR)[(size_t)(col0 + r0) * (KPAIRS) + kp + 8 + cp];      \
            fb1 = *(const float4*)&(BPTR)[(size_t)(col0 + r0 + 64) * (KPAIRS) + kp + 8 + cp]; \
        }                                                                        \
        uint32_t bhv[4][2], blv[4][2];                                           \
        _Pragma("unroll")                                                        \
        for (int nt = 0; nt < 4; nt++) {                                         \
            int cb = wn * 32 + nt * 8 + g;                                       \
            uint2 w0 = Bs[cb][t];                                                \
            uint2 w1 = Bs[cb][t + 4];                                            \
            bhv[nt][0] = w0.x; blv[nt][0] = w0.y;                                \
            bhv[nt][1] = w1.x; blv[nt][1] = w1.y;                                \
        }                                                                        \
        _Pragma("unroll")                                                        \
        for (int mt = 0; mt < 4; mt++) {                                         \
            int rb = wm * 64 + mt * 16 + g;                                      \
            uint2 a0 = As[rb][t], a1 = As[rb + 8][t];                            \
            uint2 a2 = As[rb][t + 4], a3 = As[rb + 8][t + 4];                    \
            _Pragma("unroll")                                                    \
            for (int nt = 0; nt < 4; nt++) {                                     \
                mma_bf16(acc[mt][nt], a0.x, a1.x, a2.x, a3.x, bhv[nt][0], bhv[nt][1]); \
                mma_bf16(acc[mt][nt], a0.x, a1.x, a2.x, a3.x, blv[nt][0], blv[nt][1]); \
                mma_bf16(acc[mt][nt], a0.y, a1.y, a2.y, a3.y, bhv[nt][0], bhv[nt][1]); \
            }                                                                    \
        }                                                                        \
        __syncthreads();                                                         \
    }

__global__ __launch_bounds__(256, 2)
void qkv_proj_kernel(const float* __restrict__ bq, const float* __restrict__ bk,
                     const float* __restrict__ bv)
{
    const int which = blockIdx.z;
    const uint2* __restrict__ Wsp = (which == 0) ? g_Wqs : (which == 1) ? g_Wks : g_Wvs;
    const float* __restrict__ bias = (which == 0) ? bq : (which == 1) ? bk : bv;
    const float qscale = (which == 0) ? 0.125f : 1.0f;

    __shared__ uint2 As[128][PST];
    __shared__ uint2 Bs[128][PST];

    const int tid = threadIdx.x;
    const int lane = tid & 31;
    const int warp = tid >> 5;
    const int wm = warp >> 2, wn = warp & 3;
    const int g = lane >> 2, t = lane & 3;
    const int row0 = blockIdx.x * 128;
    const int col0 = blockIdx.y * 128;

    PROJ_MAINLOOP(g_xs, Wsp, EMB / 2)

    if (which < 2) {
        uint2* __restrict__ dstp = (which == 0) ? g_Qs : g_Ks;
#pragma unroll
        for (int mt = 0; mt < 4; mt++) {
#pragma unroll
            for (int nt = 0; nt < 4; nt++) {
                int n = col0 + wn * 32 + nt * 8 + 2 * t;
                int h = n >> 6, dhp = (n & 63) >> 1;
                float2 bv2 = *(const float2*)&bias[n];
#pragma unroll
                for (int rr = 0; rr < 2; rr++) {
                    int m = row0 + wm * 64 + mt * 16 + g + rr * 8;
                    int b_idx = m >> 11, s_idx = m & 2047;
                    float v0 = (acc[mt][nt][rr * 2 + 0] + bv2.x) * qscale;
                    float v1 = (acc[mt][nt][rr * 2 + 1] + bv2.y) * qscale;
                    dstp[(((size_t)b_idx * NH + h) * SS + s_idx) * (DH / 2) + dhp] =
                        bsplit(v0, v1);
                }
            }
        }
    } else {
#pragma unroll
        for (int mt = 0; mt < 4; mt++) {
#pragma unroll
            for (int nt = 0; nt < 4; nt++) {
                int n = col0 + wn * 32 + nt * 8 + 2 * t;
                int h = n >> 6, dh = n & 63;
                float2 bv2 = *(const float2*)&bias[n];
#pragma unroll
                for (int rr = 0; rr < 2; rr++) {
                    int m = row0 + wm * 64 + mt * 16 + g + rr * 8;
                    int b_idx = m >> 11, s_idx = m & 2047;
                    float2 o2;
                    o2.x = acc[mt][nt][rr * 2 + 0] + bv2.x;
                    o2.y = acc[mt][nt][rr * 2 + 1] + bv2.y;
                    *(float2*)&g_V[(((size_t)b_idx * NH + h) * SS + s_idx) * DH + dh] = o2;
                }
            }
        }
    }
}

__global__ __launch_bounds__(256, 2)
void out_proj_kernel(const float* __restrict__ bo, float* __restrict__ out)
{
    __shared__ uint2 As[128][PST];
    __shared__ uint2 Bs[128][PST];

    const int tid = threadIdx.x;
    const int lane = tid & 31;
    const int warp = tid >> 5;
    const int wm = warp >> 2, wn = warp & 3;
    const int g = lane >> 2, t = lane & 3;
    const int row0 = blockIdx.x * 128;
    const int col0 = blockIdx.y * 128;

    PROJ_MAINLOOP(g_Os, g_Wos, HD / 2)

#pragma unroll
    for (int mt = 0; mt < 4; mt++) {
#pragma unroll
        for (int nt = 0; nt < 4; nt++) {
            int n = col0 + wn * 32 + nt * 8 + 2 * t;
            float2 bv2 = *(const float2*)&bo[n];
#pragma unroll
            for (int rr = 0; rr < 2; rr++) {
                int m = row0 + wm * 64 + mt * 16 + g + rr * 8;
                float2 o2;
                o2.x = acc[mt][nt][rr * 2 + 0] + bv2.x;
                o2.y = acc[mt][nt][rr * 2 + 1] + bv2.y;
                *(float2*)&out[(size_t)m * EMB + n] = o2;
            }
        }
    }
}

// ---------------------------------------------------------------------------
// Flash attention on pre-split Q/K/V. CTA = 128 q x (b,h), 8 warps.
// Mainloop: pure copies + MMA; only P is split in-loop.
// ---------------------------------------------------------------------------
#define AQ 128
#define AK 64
#define KST 36
#define ATT_SMEM ((64*KST + 64*KST + 128*KST) * sizeof(uint2))

__global__ __launch_bounds__(256)
void attention_kernel()
{
    extern __shared__ uint2 smu[];
    uint2 (*Ks)[KST] = (uint2(*)[KST])smu;               // [64 kv][32 d-pairs]
    uint2 (*Vp)[KST] = (uint2(*)[KST])(smu + 64 * KST);  // [64 dh][32 kv-pairs]
    uint2 (*Ps)[KST] = (uint2(*)[KST])(smu + 128 * KST); // [128 q][32 kv-pairs]

    const int tid = threadIdx.x;
    const int lane = tid & 31;
    const int w = tid >> 5;
    const int g = lane >> 2, t = lane & 3;
    const int q0 = blockIdx.x * AQ;
    const int bh = blockIdx.y;

    const uint2* __restrict__ Qg = g_Qs + ((size_t)bh * SS + q0 + w * 16) * (DH / 2);
    const uint2* __restrict__ Kg = g_Ks + (size_t)bh * SS * (DH / 2);
    const uint2* __restrict__ Vg = g_Vt + (size_t)bh * DH * (SS / 2);

    // Q fragments (pairs along d): 4 k16-tiles, hi/lo
    uint32_t qh[4][4], ql[4][4];
#pragma unroll
    for (int kt = 0; kt < 4; kt++) {
        uint2 s0 = Qg[(size_t)g * (DH / 2) + kt * 8 + t];
        uint2 s1 = Qg[(size_t)(g + 8) * (DH / 2) + kt * 8 + t];
        uint2 s2 = Qg[(size_t)g * (DH / 2) + kt * 8 + t + 4];
        uint2 s3 = Qg[(size_t)(g + 8) * (DH / 2) + kt * 8 + t + 4];
        qh[kt][0] = s0.x; ql[kt][0] = s0.y;
        qh[kt][1] = s1.x; ql[kt][1] = s1.y;
        qh[kt][2] = s2.x; ql[kt][2] = s2.y;
        qh[kt][3] = s3.x; ql[kt][3] = s3.y;
    }

    float oacc[8][4];
#pragma unroll
    for (int nt = 0; nt < 8; nt++)
#pragma unroll
        for (int e = 0; e < 4; e++) oacc[nt][e] = 0.0f;
    float m0 = -INFINITY, m1 = -INFINITY, l0 = 0.0f, l1 = 0.0f;

    for (int kv0 = 0; kv0 < SS; kv0 += AK) {
        __syncthreads();
        // K tile: 64 rows x 32 pairs; V tile: 64 dh x 32 kv-pairs. Pure copies.
#pragma unroll
        for (int u = 0; u < 4; u++) {
            int idx = tid + u * 256;       // 0..1023
            int r = idx >> 4;              // 0..63
            int f4 = (idx & 15) << 1;      // pair idx 0,2,..,30
            *(float4*)&Ks[r][f4] =
                *(const float4*)&Kg[(size_t)(kv0 + r) * (DH / 2) + f4];
            *(float4*)&Vp[r][f4] =
                *(const float4*)&Vg[(size_t)r * (SS / 2) + (kv0 >> 1) + f4];
        }
        __syncthreads();

        // ---- S = Q K^T ----
        float sacc[8][4];
#pragma unroll
        for (int nt = 0; nt < 8; nt++)
#pragma unroll
            for (int e = 0; e < 4; e++) sacc[nt][e] = 0.0f;
#pragma unroll
        for (int kt = 0; kt < 4; kt++) {
#pragma unroll
            for (int nt = 0; nt < 8; nt++) {
                uint2 w0 = Ks[nt * 8 + g][kt * 8 + t];
                uint2 w1 = Ks[nt * 8 + g][kt * 8 + t + 4];
                mma_bf16(sacc[nt], qh[kt][0], qh[kt][1], qh[kt][2], qh[kt][3], w0.x, w1.x);
                mma_bf16(sacc[nt], qh[kt][0], qh[kt][1], qh[kt][2], qh[kt][3], w0.y, w1.y);
                mma_bf16(sacc[nt], ql[kt][0], ql[kt][1], ql[kt][2], ql[kt][3], w0.x, w1.x);
            }
        }

        // ---- online softmax ----
        float mx0 = -INFINITY, mx1 = -INFINITY;
#pragma unroll
        for (int nt = 0; nt < 8; nt++) {
            mx0 = fmaxf(mx0, fmaxf(sacc[nt][0], sacc[nt][1]));
            mx1 = fmaxf(mx1, fmaxf(sacc[nt][2], sacc[nt][3]));
        }
#pragma unroll
        for (int off = 1; off < 4; off <<= 1) {
            mx0 = fmaxf(mx0, __shfl_xor_sync(0xffffffffu, mx0, off));
            mx1 = fmaxf(mx1, __shfl_xor_sync(0xffffffffu, mx1, off));
        }
        float mn0 = fmaxf(m0, mx0), mn1 = fmaxf(m1, mx1);
        float al0 = __expf(m0 - mn0), al1 = __expf(m1 - mn1);
        m0 = mn0; m1 = mn1;
        float rs0 = 0.0f, rs1 = 0.0f;
#pragma unroll
        for (int nt = 0; nt < 8; nt++) {
            sacc[nt][0] = __expf(sacc[nt][0] - mn0);
            sacc[nt][1] = __expf(sacc[nt][1] - mn0);
            sacc[nt][2] = __expf(sacc[nt][2] - mn1);
            sacc[nt][3] = __expf(sacc[nt][3] - mn1);
            rs0 += sacc[nt][0] + sacc[nt][1];
            rs1 += sacc[nt][2] + sacc[nt][3];
        }
#pragma unroll
        for (int off = 1; off < 4; off <<= 1) {
            rs0 += __shfl_xor_sync(0xffffffffu, rs0, off);
            rs1 += __shfl_xor_sync(0xffffffffu, rs1, off);
        }
        l0 = l0 * al0 + rs0;
        l1 = l1 * al1 + rs1;

        // stage P split (pairs along kv, warp-local rows)
#pragma unroll
        for (int nt = 0; nt < 8; nt++) {
            Ps[w * 16 + g][nt * 4 + t]     = bsplit(sacc[nt][0], sacc[nt][1]);
            Ps[w * 16 + g + 8][nt * 4 + t] = bsplit(sacc[nt][2], sacc[nt][3]);
        }
        __syncwarp();

#pragma unroll
        for (int nt = 0; nt < 8; nt++) {
            oacc[nt][0] *= al0; oacc[nt][1] *= al0;
            oacc[nt][2] *= al1; oacc[nt][3] *= al1;
        }

        // ---- O[q][dh] += P V ----
#pragma unroll
        for (int kt = 0; kt < 4; kt++) {
            uint2 a0 = Ps[w * 16 + g][kt * 8 + t];
            uint2 a1 = Ps[w * 16 + g + 8][kt * 8 + t];
            uint2 a2 = Ps[w * 16 + g][kt * 8 + t + 4];
            uint2 a3 = Ps[w * 16 + g + 8][kt * 8 + t + 4];
#pragma unroll
            for (int nt = 0; nt < 8; nt++) {
                uint2 w0 = Vp[nt * 8 + g][kt * 8 + t];
                uint2 w1 = Vp[nt * 8 + g][kt * 8 + t + 4];
                mma_bf16(oacc[nt], a0.x, a1.x, a2.x, a3.x, w0.x, w1.x);
                mma_bf16(oacc[nt], a0.x, a1.x, a2.x, a3.x, w0.y, w1.y);
                mma_bf16(oacc[nt], a0.y, a1.y, a2.y, a3.y, w0.x, w1.x);
            }
        }
    }

    // ---- finalize ----
    const float il0 = 1.0f / l0, il1 = 1.0f / l1;
    const int b_idx = bh >> 4, h = bh & 15;
    float* Og = g_O + ((size_t)b_idx * SS + q0 + w * 16) * HD + h * DH;
#pragma unroll
    for (int nt = 0; nt < 8; nt++) {
        int dh = nt * 8 + 2 * t;
        float2 o0 = make_float2(oacc[nt][0] * il0, oacc[nt][1] * il0);
        float2 o1 = make_float2(oacc[nt][2] * il1, oacc[nt][3] * il1);
        *(float2*)&Og[(size_t)g * HD + dh] = o0;
        *(float2*)&Og[(size_t)(g + 8) * HD + dh] = o1;
    }
}

// ---------------------------------------------------------------------------
extern "C" void kernel_launch(void* const* d_in, const int* in_sizes, int n_in,
                              void* d_out, int out_size)
{
    const float* x  = (const float*)d_in[0];
    const float* Wq = (const float*)d_in[1];
    const float* bq = (const float*)d_in[2];
    const float* Wk = (const float*)d_in[3];
    const float* bk = (const float*)d_in[4];
    const float* Wv = (const float*)d_in[5];
    const float* bv = (const float*)d_in[6];
    const float* Wo = (const float*)d_in[7];
    const float* bo = (const float*)d_in[8];
    float* out = (float*)d_out;

    cudaFuncSetAttribute(attention_kernel,
                         cudaFuncAttributeMaxDynamicSharedMemorySize,
                         (int)ATT_SMEM);

    uint2 *xs, *wqs, *wks, *wvs, *wos, *os;
    cudaGetSymbolAddress((void**)&xs,  g_xs);
    cudaGetSymbolAddress((void**)&wqs, g_Wqs);
    cudaGetSymbolAddress((void**)&wks, g_Wks);
    cudaGetSymbolAddress((void**)&wvs, g_Wvs);
    cudaGetSymbolAddress((void**)&wos, g_Wos);
    cudaGetSymbolAddress((void**)&os,  g_Os);
    float* o32;
    cudaGetSymbolAddress((void**)&o32, g_O);

    const int NP_X = MROWS * EMB / 2;
    const int NP_W = HD * EMB / 2;
    split_kernel<<<(NP_X + 255) / 256, 256>>>(x,  xs,  NP_X);
    split_kernel<<<(NP_W + 255) / 256, 256>>>(Wq, wqs, NP_W);
    split_kernel<<<(NP_W + 255) / 256, 256>>>(Wk, wks, NP_W);
    split_kernel<<<(NP_W + 255) / 256, 256>>>(Wv, wvs, NP_W);
    split_kernel<<<(NP_W + 255) / 256, 256>>>(Wo, wos, NP_W);

    dim3 gProj(MROWS / 128, HD / 128, 3);
    qkv_proj_kernel<<<gProj, 256>>>(bq, bk, bv);

    dim3 gVt(SS / 64, BH);
    vtrans_kernel<<<gVt, 256>>>();

    dim3 gAtt(SS / AQ, BH);
    attention_kernel<<<gAtt, 256, ATT_SMEM>>>();

    const int NP_O = MROWS * HD / 2;
    split_kernel<<<(NP_O + 255) / 256, 256>>>(o32, os, NP_O);

    dim3 gOut(MROWS / 128, EMB / 128);
    out_proj_kernel<<<gOut, 256>>>(bo, out);
}